// round 15
// baseline (speedup 1.0000x reference)
#include <cuda_runtime.h>
#include <cuda_bf16.h>
#include <math.h>
#include <stdint.h>

#define BB 32
#define SS 2048
#define HH 1024
#define SC 16
#define ROWS (BB*SS)          // 65536
#define NCHUNK 8
#define VKS 64                // v split-K factor

// ---------------- device scratch (no allocs allowed) ----------------
__device__ __nv_bfloat16 g_Xb[(size_t)ROWS * HH];   // 128 MB bf16 X
__device__ __nv_bfloat16 g_Wt1[HH * HH];            // W1^T bf16 [d][k]
__device__ __nv_bfloat16 g_Wt2[HH * HH];            // W2^T bf16
__device__ float g_partial[BB * SC * HH];           // mean-pass partials
__device__ float g_v1[BB * HH];
__device__ float g_v2[BB * HH];
__device__ float g_vpart[2 * VKS * BB * HH];        // split-k partials for v
__device__ float g_pU[2 * NCHUNK * ROWS];           // [hop][nch][row] coalesced

// ---------------- helpers ----------------
__device__ __forceinline__ uint32_t sm_u32(const void* p) {
    uint32_t a;
    asm("{ .reg .u64 t; cvta.to.shared.u64 t, %1; cvt.u32.u64 %0, t; }" : "=r"(a) : "l"(p));
    return a;
}
__device__ __forceinline__ float ftanh(float x) {
    float y; asm("tanh.approx.f32 %0, %1;" : "=f"(y) : "f"(x)); return y;
}

#define CP16(dst, src) \
    asm volatile("cp.async.cg.shared.global [%0], [%1], 16;\n" \
        :: "r"(dst), "l"(__cvta_generic_to_global(src)))
#define CP_COMMIT()    asm volatile("cp.async.commit_group;\n" ::: "memory")
#define CP_WAIT(n)     asm volatile("cp.async.wait_group %0;\n" :: "n"(n) : "memory")

__device__ __forceinline__ void ldsm4(uint32_t& r0, uint32_t& r1, uint32_t& r2, uint32_t& r3, uint32_t a) {
    asm volatile("ldmatrix.sync.aligned.m8n8.x4.shared.b16 {%0,%1,%2,%3}, [%4];"
        : "=r"(r0), "=r"(r1), "=r"(r2), "=r"(r3) : "r"(a));
}
__device__ __forceinline__ void mma16816(float* d, const uint32_t* a, const uint32_t* b) {
    asm volatile("mma.sync.aligned.m16n8k16.row.col.f32.bf16.bf16.f32 "
        "{%0,%1,%2,%3}, {%4,%5,%6,%7}, {%8,%9}, {%0,%1,%2,%3};"
        : "+f"(d[0]), "+f"(d[1]), "+f"(d[2]), "+f"(d[3])
        : "r"(a[0]), "r"(a[1]), "r"(a[2]), "r"(a[3]), "r"(b[0]), "r"(b[1]));
}

// ---------------- SMEM layout for GEMM (3-stage) ----------------
#define SMA 0               // 3 x 16384
#define SMB 49152           // 3 x 16384
#define SMV 98304           // 128 floats of v
#define SMU 98816           // Upart[4][128] floats
#define SM_TOTAL 100864

// ---------------------------------------------------------------
// convert W -> bf16 transposed: Wt[d][k] = bf16(W[k][d])
// ---------------------------------------------------------------
__global__ void convW(const float* __restrict__ W1, const float* __restrict__ W2) {
    __shared__ float t[32][33];
    const float* W = blockIdx.z ? W2 : W1;
    __nv_bfloat16* Wt = blockIdx.z ? g_Wt2 : g_Wt1;
    int d0 = blockIdx.x * 32, k0 = blockIdx.y * 32;
    int tx = threadIdx.x, ty = threadIdx.y;
    for (int j = ty; j < 32; j += 8)
        t[j][tx] = W[(size_t)(k0 + j) * HH + d0 + tx];
    __syncthreads();
    for (int j = ty; j < 32; j += 8)
        Wt[(size_t)(d0 + j) * HH + k0 + tx] = __float2bfloat16(t[tx][j]);
}

// ---------------------------------------------------------------
// convert X -> bf16 (streaming store) + partial column sums
// grid (SC, BB), block 256
// ---------------------------------------------------------------
__global__ void __launch_bounds__(256) convX_mean(const float* __restrict__ X) {
    int sc = blockIdx.x, b = blockIdx.y;
    int h0 = threadIdx.x * 4;
    size_t base = ((size_t)b * SS + (size_t)sc * 128) * HH + h0;
    float a0 = 0.f, a1 = 0.f, a2 = 0.f, a3 = 0.f;
#pragma unroll 8
    for (int i = 0; i < 128; i++) {
        float4 x = *(const float4*)(X + base + (size_t)i * HH);
        a0 += x.x; a1 += x.y; a2 += x.z; a3 += x.w;
        __nv_bfloat162 p0 = __floats2bfloat162_rn(x.x, x.y);
        __nv_bfloat162 p1 = __floats2bfloat162_rn(x.z, x.w);
        uint2 u;
        u.x = *(uint32_t*)&p0;
        u.y = *(uint32_t*)&p1;
        __stcs((uint2*)(g_Xb + base + (size_t)i * HH), u);   // evict-first
    }
    *(float4*)(g_partial + (b * SC + sc) * HH + h0) = make_float4(a0, a1, a2, a3);
}

// ---------------------------------------------------------------
// v partials: split-K(64) over Wm. grid (8 dtile, 64 ksplit, 2 hop), 256 thr.
// m0 slice recomputed in-block from g_partial.
// ---------------------------------------------------------------
__global__ void __launch_bounds__(256) prep_v_part(
        const float* __restrict__ Wm1, const float* __restrict__ Wm2,
        const float* __restrict__ q) {
    __shared__ float sm0[16 * 32];             // [k][b]
    int hop = blockIdx.z, ks = blockIdx.y, dt = blockIdx.x;
    const float* Wm = hop ? Wm2 : Wm1;
    int d0 = dt * 128, k0 = ks * 16;

    for (int i = threadIdx.x; i < 16 * 32; i += 256) {
        int k = i & 15, b = i >> 4;
        float s = 0.f;
#pragma unroll
        for (int c = 0; c < SC; c++)
            s += g_partial[(b * SC + c) * HH + k0 + k];
        sm0[k * 32 + b] = s * (1.f / (float)SS) * q[b * HH + k0 + k];
    }
    __syncthreads();

    int dl = (threadIdx.x & 31) * 4;
    int bg = (threadIdx.x >> 5) * 4;
    const float* Wp = Wm + (size_t)k0 * HH + d0 + dl;

    float acc[4][4];
#pragma unroll
    for (int j = 0; j < 4; j++)
#pragma unroll
        for (int t = 0; t < 4; t++) acc[j][t] = 0.f;

#pragma unroll
    for (int half = 0; half < 2; half++) {
        float4 wv[8];
#pragma unroll
        for (int k = 0; k < 8; k++)
            wv[k] = *(const float4*)(Wp + (size_t)(half * 8 + k) * HH);
#pragma unroll
        for (int k = 0; k < 8; k++) {
            const float* mk = sm0 + (half * 8 + k) * 32 + bg;
#pragma unroll
            for (int j = 0; j < 4; j++) {
                float m = mk[j];
                acc[j][0] = fmaf(m, wv[k].x, acc[j][0]);
                acc[j][1] = fmaf(m, wv[k].y, acc[j][1]);
                acc[j][2] = fmaf(m, wv[k].z, acc[j][2]);
                acc[j][3] = fmaf(m, wv[k].w, acc[j][3]);
            }
        }
    }
    float* dst = g_vpart + (size_t)(hop * VKS + ks) * BB * HH;
#pragma unroll
    for (int j = 0; j < 4; j++)
        *(float4*)(dst + (bg + j) * HH + d0 + dl) =
            make_float4(acc[j][0], acc[j][1], acc[j][2], acc[j][3]);
}

// ---------------------------------------------------------------
// finalize v (both hops) + write u_att0 (mean) to out[0] slot.
// grid 2*BB*HH/256. 4 independent accumulator chains for ILP.
// ---------------------------------------------------------------
__global__ void finalize_v(const float* __restrict__ Wh1, const float* __restrict__ Wh2,
                           float* __restrict__ out) {
    int idx = blockIdx.x * 256 + threadIdx.x;    // < 2*BB*HH
    int hop = idx >> 15;
    int r = idx & (BB * HH - 1);
    int d = r & (HH - 1);
    const float* vp = g_vpart + (size_t)hop * VKS * BB * HH + r;
    float s0 = 0.f, s1 = 0.f, s2 = 0.f, s3 = 0.f;
#pragma unroll 4
    for (int ks = 0; ks < VKS; ks += 4) {
        s0 += __ldcs(vp + (size_t)(ks + 0) * BB * HH);
        s1 += __ldcs(vp + (size_t)(ks + 1) * BB * HH);
        s2 += __ldcs(vp + (size_t)(ks + 2) * BB * HH);
        s3 += __ldcs(vp + (size_t)(ks + 3) * BB * HH);
    }
    float s = (s0 + s1) + (s2 + s3);
    float scale = hop ? 2.f : 1.f;
    const float* Wh = hop ? Wh2 : Wh1;
    (hop ? g_v2 : g_v1)[r] = tanhf(scale * s) * Wh[d];

    if (hop == 0) {                              // u_att0 = mean
        int b = r >> 10, h = r & (HH - 1);
        float m = 0.f;
#pragma unroll
        for (int c = 0; c < SC; c++)
            m += g_partial[(b * SC + c) * HH + h];
        out[r] = m * (1.f / (float)SS);
    }
}

// ---------------------------------------------------------------
// HMMA GEMM + fused tanh/v-dot epilogue. 3-stage cp.async pipeline.
// grid (NCHUNK*2, ROWS/128): x = nch*2 + hop (hop fastest for X L2 reuse).
// ---------------------------------------------------------------
__device__ __forceinline__ void stage_load(uint32_t sb, int st,
                                           const __nv_bfloat16* Xrow,
                                           const __nv_bfloat16* Wrow,
                                           int k0, int tid) {
    uint32_t ab = sb + SMA + st * 16384;
    uint32_t bb = sb + SMB + st * 16384;
#pragma unroll
    for (int i = 0; i < 4; i++) {
        int c = tid + i * 256;            // 1024 16B-chunks
        int r = c >> 3, seg = c & 7;
        uint32_t off = (uint32_t)(r * 128 + seg * 16);
        uint32_t sw  = off ^ ((off >> 3) & 0x70);
        CP16(ab + sw, (const char*)(Xrow + (size_t)r * HH + k0) + seg * 16);
        CP16(bb + sw, (const char*)(Wrow + (size_t)r * HH + k0) + seg * 16);
    }
}

__global__ void __launch_bounds__(256, 2) gemm_mma() {
    extern __shared__ char smem[];
    uint32_t sb = sm_u32(smem);
    int tid = threadIdx.x, lane = tid & 31, wid = tid >> 5;
    int warpM = wid & 1, warpN = wid >> 1;           // 2 x 4
    int hop = blockIdx.x & 1, nch = blockIdx.x >> 1;
    int rowt = blockIdx.y;
    int row0 = rowt * 128, n0 = nch * 128;
    int b = rowt >> 4;

    const __nv_bfloat16* Xrow = g_Xb + (size_t)row0 * HH;
    const __nv_bfloat16* Wrow = (hop ? g_Wt2 : g_Wt1) + (size_t)n0 * HH;
    const float* v = (hop ? g_v2 : g_v1) + b * HH + n0;

    float* vs = (float*)(smem + SMV);
    float* su = (float*)(smem + SMU);
    if (tid < 128) vs[tid] = v[tid];

    float acc[4][4][4];
#pragma unroll
    for (int i = 0; i < 4; i++)
#pragma unroll
        for (int j = 0; j < 4; j++)
#pragma unroll
            for (int t = 0; t < 4; t++) acc[i][j][t] = 0.f;

    int rA = warpM * 64 + (lane & 15);
    uint32_t rxA = (uint32_t)((rA & 7) << 4);
    uint32_t aoff = (uint32_t)(((lane >> 4) & 1) << 4);
    int rB = warpN * 32 + (lane & 7) + ((lane & 16) >> 1);
    uint32_t rxB = (uint32_t)((rB & 7) << 4);
    uint32_t boff = (uint32_t)(((lane >> 3) & 1) << 4);

    stage_load(sb, 0, Xrow, Wrow, 0,   tid); CP_COMMIT();
    stage_load(sb, 1, Xrow, Wrow, 64,  tid); CP_COMMIT();
    stage_load(sb, 2, Xrow, Wrow, 128, tid); CP_COMMIT();

    int st = 0;
    for (int kk = 0; kk < 16; kk++) {
        if (kk < 14) { CP_WAIT(2); }
        else if (kk == 14) { CP_WAIT(1); }
        else { CP_WAIT(0); }
        __syncthreads();

        uint32_t abase = sb + SMA + st * 16384;
        uint32_t bbase = sb + SMB + st * 16384;
#pragma unroll
        for (int s = 0; s < 4; s++) {
            uint32_t A[4][4];
#pragma unroll
            for (int i = 0; i < 4; i++) {
                uint32_t addr = abase + (uint32_t)((rA + i * 16) * 128)
                              + (((uint32_t)(s * 32) + aoff) ^ rxA);
                ldsm4(A[i][0], A[i][1], A[i][2], A[i][3], addr);
            }
            uint32_t Bf[4][2];
#pragma unroll
            for (int jj = 0; jj < 2; jj++) {
                uint32_t addr = bbase + (uint32_t)((rB + jj * 16) * 128)
                              + (((uint32_t)(s * 32) + boff) ^ rxB);
                ldsm4(Bf[jj*2][0], Bf[jj*2][1], Bf[jj*2+1][0], Bf[jj*2+1][1], addr);
            }
#pragma unroll
            for (int i = 0; i < 4; i++)
#pragma unroll
                for (int j = 0; j < 4; j++)
                    mma16816(acc[i][j], A[i], Bf[j]);
        }
        __syncthreads();
        if (kk < 13) {
            stage_load(sb, st, Xrow, Wrow, (kk + 3) * 64, tid);
            CP_COMMIT();
        }
        st = (st == 2) ? 0 : st + 1;
    }

    // epilogue: tanh * v, reduce over n
    float vv[4][2];
#pragma unroll
    for (int j = 0; j < 4; j++) {
        int nl = warpN * 32 + j * 8 + (lane & 3) * 2;
        vv[j][0] = vs[nl]; vv[j][1] = vs[nl + 1];
    }
#pragma unroll
    for (int i = 0; i < 4; i++) {
        float r0 = 0.f, r1 = 0.f;
#pragma unroll
        for (int j = 0; j < 4; j++) {
            r0 = fmaf(ftanh(acc[i][j][0]), vv[j][0], r0);
            r0 = fmaf(ftanh(acc[i][j][1]), vv[j][1], r0);
            r1 = fmaf(ftanh(acc[i][j][2]), vv[j][0], r1);
            r1 = fmaf(ftanh(acc[i][j][3]), vv[j][1], r1);
        }
        r0 += __shfl_xor_sync(0xffffffffu, r0, 1);
        r0 += __shfl_xor_sync(0xffffffffu, r0, 2);
        r1 += __shfl_xor_sync(0xffffffffu, r1, 1);
        r1 += __shfl_xor_sync(0xffffffffu, r1, 2);
        if ((lane & 3) == 0) {
            int r = warpM * 64 + i * 16 + (lane >> 2);
            su[warpN * 128 + r]     = r0;
            su[warpN * 128 + r + 8] = r1;
        }
    }
    __syncthreads();
    if (tid < 128) {
        float s = su[tid] + su[128 + tid] + su[256 + tid] + su[384 + tid];
        g_pU[((size_t)(hop * NCHUNK + nch)) * ROWS + row0 + tid] = s;
    }
}

// ---------------------------------------------------------------
// fused: reduce pU -> softmax (recomputed per block, identical in all
// blocks of a batch) -> weighted column sums -> out. One fp32 X pass.
// grid (8 hchunk, BB), block 512. pU read with float4 (4 rows/thread).
// ---------------------------------------------------------------
__global__ void __launch_bounds__(512) colsum_out(const float* __restrict__ X,
                                                  float* __restrict__ out) {
    __shared__ float sa[2 * SS];            // alpha, both hops (16 KB)
    __shared__ float su[2 * 16 * 128];      // per-warp partials (16 KB)
    __shared__ float red[512];
    int hc = blockIdx.x, b = blockIdx.y;
    int tid = threadIdx.x, w = tid >> 5, lane = tid & 31;

    // --- softmax (both hops), recomputed identically in every hc block ---
#pragma unroll
    for (int hop = 0; hop < 2; hop++) {
        // thread owns 4 consecutive rows: [b*SS + tid*4, +4)
        float4 u = make_float4(0.f, 0.f, 0.f, 0.f);
        {
            size_t base = (size_t)b * SS + tid * 4;
#pragma unroll
            for (int c = 0; c < NCHUNK; c++) {
                float4 p = *(const float4*)(g_pU + ((size_t)(hop * NCHUNK + c)) * ROWS + base);
                u.x += p.x; u.y += p.y; u.z += p.z; u.w += p.w;
            }
        }
        float m = fmaxf(fmaxf(u.x, u.y), fmaxf(u.z, u.w));
        red[tid] = m; __syncthreads();
        for (int o = 256; o > 0; o >>= 1) {
            if (tid < o) red[tid] = fmaxf(red[tid], red[tid + o]);
            __syncthreads();
        }
        float mx = red[0]; __syncthreads();
        float e0 = expf(u.x - mx), e1 = expf(u.y - mx);
        float e2 = expf(u.z - mx), e3 = expf(u.w - mx);
        red[tid] = (e0 + e1) + (e2 + e3); __syncthreads();
        for (int o = 256; o > 0; o >>= 1) {
            if (tid < o) red[tid] += red[tid + o];
            __syncthreads();
        }
        float inv = 1.f / red[0]; __syncthreads();
        *(float4*)(sa + hop * SS + tid * 4) =
            make_float4(e0 * inv, e1 * inv, e2 * inv, e3 * inv);
        __syncthreads();
    }

    // --- weighted column sums: warp w owns rows [w*128,(w+1)*128) ---
    int h0 = hc * 128 + lane * 4;
    size_t base = ((size_t)b * SS + (size_t)w * 128) * HH + h0;
    const float* a1 = sa + w * 128;
    const float* a2 = sa + SS + w * 128;
    float4 c1 = make_float4(0.f, 0.f, 0.f, 0.f);
    float4 c2 = make_float4(0.f, 0.f, 0.f, 0.f);
#pragma unroll 8
    for (int i = 0; i < 128; i++) {
        float4 x = __ldcs((const float4*)(X + base + (size_t)i * HH));
        float w1 = a1[i], w2 = a2[i];
        c1.x = fmaf(w1, x.x, c1.x); c1.y = fmaf(w1, x.y, c1.y);
        c1.z = fmaf(w1, x.z, c1.z); c1.w = fmaf(w1, x.w, c1.w);
        c2.x = fmaf(w2, x.x, c2.x); c2.y = fmaf(w2, x.y, c2.y);
        c2.z = fmaf(w2, x.z, c2.z); c2.w = fmaf(w2, x.w, c2.w);
    }
    *(float4*)(su + (0 * 16 + w) * 128 + lane * 4) = c1;
    *(float4*)(su + (1 * 16 + w) * 128 + lane * 4) = c2;
    __syncthreads();

    if (tid < 256) {
        int hop = tid >> 7, h = tid & 127;
        float s = 0.f;
#pragma unroll
        for (int ww = 0; ww < 16; ww++)
            s += su[(hop * 16 + ww) * 128 + h];
        out[(size_t)(1 + hop) * BB * HH + b * HH + hc * 128 + h] = s;
    }
}

// ---------------------------------------------------------------
extern "C" void kernel_launch(void* const* d_in, const int* in_sizes, int n_in,
                              void* d_out, int out_size) {
    (void)in_sizes; (void)n_in; (void)out_size;
    const float* X   = (const float*)d_in[0];
    const float* q   = (const float*)d_in[1];
    const float* W1  = (const float*)d_in[2];
    const float* Wm1 = (const float*)d_in[3];
    const float* Wh1 = (const float*)d_in[4];
    const float* W2  = (const float*)d_in[5];
    const float* Wm2 = (const float*)d_in[6];
    const float* Wh2 = (const float*)d_in[7];
    float* out = (float*)d_out;

    cudaFuncSetAttribute(gemm_mma, cudaFuncAttributeMaxDynamicSharedMemorySize, SM_TOTAL);

    convW<<<dim3(32, 32, 2), dim3(32, 8)>>>(W1, W2);
    convX_mean<<<dim3(SC, BB), 256>>>(X);
    prep_v_part<<<dim3(8, VKS, 2), 256>>>(Wm1, Wm2, q);
    finalize_v<<<2 * BB * HH / 256, 256>>>(Wh1, Wh2, out);

    gemm_mma<<<dim3(NCHUNK * 2, ROWS / 128), 256, SM_TOTAL>>>();

    colsum_out<<<dim3(8, BB), 512>>>(X, out);
}

// round 16
// speedup vs baseline: 1.0116x; 1.0116x over previous
#include <cuda_runtime.h>
#include <cuda_bf16.h>
#include <math.h>
#include <stdint.h>

#define BB 32
#define SS 2048
#define HH 1024
#define SC 16
#define ROWS (BB*SS)          // 65536
#define NCHUNK 8
#define VKS 64                // v split-K factor

// ---------------- device scratch (no allocs allowed) ----------------
__device__ __nv_bfloat16 g_Xb[(size_t)ROWS * HH];   // 128 MB bf16 X
__device__ __nv_bfloat16 g_Wt1[HH * HH];            // W1^T bf16 [d][k]
__device__ __nv_bfloat16 g_Wt2[HH * HH];            // W2^T bf16
__device__ float g_partial[BB * SC * HH];           // mean-pass partials
__device__ float g_v1[BB * HH];
__device__ float g_v2[BB * HH];
__device__ float g_vpart[2 * VKS * BB * HH];        // split-k partials for v
__device__ float g_pU[2 * NCHUNK * ROWS];           // [hop][nch][row] coalesced

// ---------------- helpers ----------------
__device__ __forceinline__ uint32_t sm_u32(const void* p) {
    uint32_t a;
    asm("{ .reg .u64 t; cvta.to.shared.u64 t, %1; cvt.u32.u64 %0, t; }" : "=r"(a) : "l"(p));
    return a;
}
__device__ __forceinline__ float ftanh(float x) {
    float y; asm("tanh.approx.f32 %0, %1;" : "=f"(y) : "f"(x)); return y;
}

#define CP16(dst, src) \
    asm volatile("cp.async.cg.shared.global [%0], [%1], 16;\n" \
        :: "r"(dst), "l"(__cvta_generic_to_global(src)))
#define CP_COMMIT()    asm volatile("cp.async.commit_group;\n" ::: "memory")
#define CP_WAIT(n)     asm volatile("cp.async.wait_group %0;\n" :: "n"(n) : "memory")

__device__ __forceinline__ void ldsm4(uint32_t& r0, uint32_t& r1, uint32_t& r2, uint32_t& r3, uint32_t a) {
    asm volatile("ldmatrix.sync.aligned.m8n8.x4.shared.b16 {%0,%1,%2,%3}, [%4];"
        : "=r"(r0), "=r"(r1), "=r"(r2), "=r"(r3) : "r"(a));
}
__device__ __forceinline__ void mma16816(float* d, const uint32_t* a, const uint32_t* b) {
    asm volatile("mma.sync.aligned.m16n8k16.row.col.f32.bf16.bf16.f32 "
        "{%0,%1,%2,%3}, {%4,%5,%6,%7}, {%8,%9}, {%0,%1,%2,%3};"
        : "+f"(d[0]), "+f"(d[1]), "+f"(d[2]), "+f"(d[3])
        : "r"(a[0]), "r"(a[1]), "r"(a[2]), "r"(a[3]), "r"(b[0]), "r"(b[1]));
}

// ---------------- SMEM layout for GEMM (3-stage) ----------------
#define SMA 0               // 3 x 16384
#define SMB 49152           // 3 x 16384
#define SMV 98304           // 128 floats of v
#define SMU 98816           // Upart[4][128] floats
#define SM_TOTAL 100864

// ---------------------------------------------------------------
// Fused first pass: blocks [0,512) = convX (bf16 convert + colsum partials),
// blocks [512,2560) = convW (transpose W -> bf16). Independent work.
// ---------------------------------------------------------------
__global__ void __launch_bounds__(256) conv_fused(const float* __restrict__ X,
                                                  const float* __restrict__ W1,
                                                  const float* __restrict__ W2) {
    if (blockIdx.x < 512) {
        // ---- convX_mean ----
        int sc = blockIdx.x & 15, b = blockIdx.x >> 4;
        int h0 = threadIdx.x * 4;
        size_t base = ((size_t)b * SS + (size_t)sc * 128) * HH + h0;
        float a0 = 0.f, a1 = 0.f, a2 = 0.f, a3 = 0.f;
#pragma unroll 8
        for (int i = 0; i < 128; i++) {
            float4 x = *(const float4*)(X + base + (size_t)i * HH);
            a0 += x.x; a1 += x.y; a2 += x.z; a3 += x.w;
            __nv_bfloat162 p0 = __floats2bfloat162_rn(x.x, x.y);
            __nv_bfloat162 p1 = __floats2bfloat162_rn(x.z, x.w);
            uint2 u;
            u.x = *(uint32_t*)&p0;
            u.y = *(uint32_t*)&p1;
            __stcs((uint2*)(g_Xb + base + (size_t)i * HH), u);   // evict-first
        }
        *(float4*)(g_partial + (b * SC + sc) * HH + h0) = make_float4(a0, a1, a2, a3);
    } else {
        // ---- convW: m in [0,2048): 32 dtiles x 32 ktiles x 2 hops ----
        __shared__ float t[32][33];
        int m = blockIdx.x - 512;
        int hop = m >> 10;
        int d0 = (m & 31) * 32, k0 = ((m >> 5) & 31) * 32;
        const float* W = hop ? W2 : W1;
        __nv_bfloat16* Wt = hop ? g_Wt2 : g_Wt1;
        int tx = threadIdx.x & 31, ty = threadIdx.x >> 5;
        for (int j = ty; j < 32; j += 8)
            t[j][tx] = W[(size_t)(k0 + j) * HH + d0 + tx];
        __syncthreads();
        for (int j = ty; j < 32; j += 8)
            Wt[(size_t)(d0 + j) * HH + k0 + tx] = __float2bfloat16(t[tx][j]);
    }
}

// ---------------------------------------------------------------
// v partials: split-K(64) over Wm. grid (8 dtile, 64 ksplit, 2 hop), 256 thr.
// m0 slice recomputed in-block from g_partial.
// ---------------------------------------------------------------
__global__ void __launch_bounds__(256) prep_v_part(
        const float* __restrict__ Wm1, const float* __restrict__ Wm2,
        const float* __restrict__ q) {
    __shared__ float sm0[16 * 32];             // [k][b]
    int hop = blockIdx.z, ks = blockIdx.y, dt = blockIdx.x;
    const float* Wm = hop ? Wm2 : Wm1;
    int d0 = dt * 128, k0 = ks * 16;

    for (int i = threadIdx.x; i < 16 * 32; i += 256) {
        int k = i & 15, b = i >> 4;
        float s = 0.f;
#pragma unroll
        for (int c = 0; c < SC; c++)
            s += g_partial[(b * SC + c) * HH + k0 + k];
        sm0[k * 32 + b] = s * (1.f / (float)SS) * q[b * HH + k0 + k];
    }
    __syncthreads();

    int dl = (threadIdx.x & 31) * 4;
    int bg = (threadIdx.x >> 5) * 4;
    const float* Wp = Wm + (size_t)k0 * HH + d0 + dl;

    float acc[4][4];
#pragma unroll
    for (int j = 0; j < 4; j++)
#pragma unroll
        for (int t = 0; t < 4; t++) acc[j][t] = 0.f;

#pragma unroll
    for (int half = 0; half < 2; half++) {
        float4 wv[8];
#pragma unroll
        for (int k = 0; k < 8; k++)
            wv[k] = *(const float4*)(Wp + (size_t)(half * 8 + k) * HH);
#pragma unroll
        for (int k = 0; k < 8; k++) {
            const float* mk = sm0 + (half * 8 + k) * 32 + bg;
#pragma unroll
            for (int j = 0; j < 4; j++) {
                float m = mk[j];
                acc[j][0] = fmaf(m, wv[k].x, acc[j][0]);
                acc[j][1] = fmaf(m, wv[k].y, acc[j][1]);
                acc[j][2] = fmaf(m, wv[k].z, acc[j][2]);
                acc[j][3] = fmaf(m, wv[k].w, acc[j][3]);
            }
        }
    }
    float* dst = g_vpart + (size_t)(hop * VKS + ks) * BB * HH;
#pragma unroll
    for (int j = 0; j < 4; j++)
        *(float4*)(dst + (bg + j) * HH + d0 + dl) =
            make_float4(acc[j][0], acc[j][1], acc[j][2], acc[j][3]);
}

// ---------------------------------------------------------------
// finalize v (both hops) + write u_att0 (mean) to out[0] slot.
// grid 2*BB*HH/256. 4 independent accumulator chains for ILP.
// ---------------------------------------------------------------
__global__ void finalize_v(const float* __restrict__ Wh1, const float* __restrict__ Wh2,
                           float* __restrict__ out) {
    int idx = blockIdx.x * 256 + threadIdx.x;    // < 2*BB*HH
    int hop = idx >> 15;
    int r = idx & (BB * HH - 1);
    int d = r & (HH - 1);
    const float* vp = g_vpart + (size_t)hop * VKS * BB * HH + r;
    float s0 = 0.f, s1 = 0.f, s2 = 0.f, s3 = 0.f;
#pragma unroll 4
    for (int ks = 0; ks < VKS; ks += 4) {
        s0 += __ldcs(vp + (size_t)(ks + 0) * BB * HH);
        s1 += __ldcs(vp + (size_t)(ks + 1) * BB * HH);
        s2 += __ldcs(vp + (size_t)(ks + 2) * BB * HH);
        s3 += __ldcs(vp + (size_t)(ks + 3) * BB * HH);
    }
    float s = (s0 + s1) + (s2 + s3);
    float scale = hop ? 2.f : 1.f;
    const float* Wh = hop ? Wh2 : Wh1;
    (hop ? g_v2 : g_v1)[r] = tanhf(scale * s) * Wh[d];

    if (hop == 0) {                              // u_att0 = mean
        int b = r >> 10, h = r & (HH - 1);
        float m = 0.f;
#pragma unroll
        for (int c = 0; c < SC; c++)
            m += g_partial[(b * SC + c) * HH + h];
        out[r] = m * (1.f / (float)SS);
    }
}

// ---------------------------------------------------------------
// HMMA GEMM + fused tanh/v-dot epilogue. 3-stage cp.async pipeline.
// grid (NCHUNK*2, ROWS/128): x = nch*2 + hop (hop fastest for X L2 reuse).
// ---------------------------------------------------------------
__device__ __forceinline__ void stage_load(uint32_t sb, int st,
                                           const __nv_bfloat16* Xrow,
                                           const __nv_bfloat16* Wrow,
                                           int k0, int tid) {
    uint32_t ab = sb + SMA + st * 16384;
    uint32_t bb = sb + SMB + st * 16384;
#pragma unroll
    for (int i = 0; i < 4; i++) {
        int c = tid + i * 256;            // 1024 16B-chunks
        int r = c >> 3, seg = c & 7;
        uint32_t off = (uint32_t)(r * 128 + seg * 16);
        uint32_t sw  = off ^ ((off >> 3) & 0x70);
        CP16(ab + sw, (const char*)(Xrow + (size_t)r * HH + k0) + seg * 16);
        CP16(bb + sw, (const char*)(Wrow + (size_t)r * HH + k0) + seg * 16);
    }
}

__global__ void __launch_bounds__(256, 2) gemm_mma() {
    extern __shared__ char smem[];
    uint32_t sb = sm_u32(smem);
    int tid = threadIdx.x, lane = tid & 31, wid = tid >> 5;
    int warpM = wid & 1, warpN = wid >> 1;           // 2 x 4
    int hop = blockIdx.x & 1, nch = blockIdx.x >> 1;
    int rowt = blockIdx.y;
    int row0 = rowt * 128, n0 = nch * 128;
    int b = rowt >> 4;

    const __nv_bfloat16* Xrow = g_Xb + (size_t)row0 * HH;
    const __nv_bfloat16* Wrow = (hop ? g_Wt2 : g_Wt1) + (size_t)n0 * HH;
    const float* v = (hop ? g_v2 : g_v1) + b * HH + n0;

    float* vs = (float*)(smem + SMV);
    float* su = (float*)(smem + SMU);
    if (tid < 128) vs[tid] = v[tid];

    float acc[4][4][4];
#pragma unroll
    for (int i = 0; i < 4; i++)
#pragma unroll
        for (int j = 0; j < 4; j++)
#pragma unroll
            for (int t = 0; t < 4; t++) acc[i][j][t] = 0.f;

    int rA = warpM * 64 + (lane & 15);
    uint32_t rxA = (uint32_t)((rA & 7) << 4);
    uint32_t aoff = (uint32_t)(((lane >> 4) & 1) << 4);
    int rB = warpN * 32 + (lane & 7) + ((lane & 16) >> 1);
    uint32_t rxB = (uint32_t)((rB & 7) << 4);
    uint32_t boff = (uint32_t)(((lane >> 3) & 1) << 4);

    stage_load(sb, 0, Xrow, Wrow, 0,   tid); CP_COMMIT();
    stage_load(sb, 1, Xrow, Wrow, 64,  tid); CP_COMMIT();
    stage_load(sb, 2, Xrow, Wrow, 128, tid); CP_COMMIT();

    int st = 0;
    for (int kk = 0; kk < 16; kk++) {
        if (kk < 14) { CP_WAIT(2); }
        else if (kk == 14) { CP_WAIT(1); }
        else { CP_WAIT(0); }
        __syncthreads();

        uint32_t abase = sb + SMA + st * 16384;
        uint32_t bbase = sb + SMB + st * 16384;
#pragma unroll
        for (int s = 0; s < 4; s++) {
            uint32_t A[4][4];
#pragma unroll
            for (int i = 0; i < 4; i++) {
                uint32_t addr = abase + (uint32_t)((rA + i * 16) * 128)
                              + (((uint32_t)(s * 32) + aoff) ^ rxA);
                ldsm4(A[i][0], A[i][1], A[i][2], A[i][3], addr);
            }
            uint32_t Bf[4][2];
#pragma unroll
            for (int jj = 0; jj < 2; jj++) {
                uint32_t addr = bbase + (uint32_t)((rB + jj * 16) * 128)
                              + (((uint32_t)(s * 32) + boff) ^ rxB);
                ldsm4(Bf[jj*2][0], Bf[jj*2][1], Bf[jj*2+1][0], Bf[jj*2+1][1], addr);
            }
#pragma unroll
            for (int i = 0; i < 4; i++)
#pragma unroll
                for (int j = 0; j < 4; j++)
                    mma16816(acc[i][j], A[i], Bf[j]);
        }
        __syncthreads();
        if (kk < 13) {
            stage_load(sb, st, Xrow, Wrow, (kk + 3) * 64, tid);
            CP_COMMIT();
        }
        st = (st == 2) ? 0 : st + 1;
    }

    // epilogue: tanh * v, reduce over n
    float vv[4][2];
#pragma unroll
    for (int j = 0; j < 4; j++) {
        int nl = warpN * 32 + j * 8 + (lane & 3) * 2;
        vv[j][0] = vs[nl]; vv[j][1] = vs[nl + 1];
    }
#pragma unroll
    for (int i = 0; i < 4; i++) {
        float r0 = 0.f, r1 = 0.f;
#pragma unroll
        for (int j = 0; j < 4; j++) {
            r0 = fmaf(ftanh(acc[i][j][0]), vv[j][0], r0);
            r0 = fmaf(ftanh(acc[i][j][1]), vv[j][1], r0);
            r1 = fmaf(ftanh(acc[i][j][2]), vv[j][0], r1);
            r1 = fmaf(ftanh(acc[i][j][3]), vv[j][1], r1);
        }
        r0 += __shfl_xor_sync(0xffffffffu, r0, 1);
        r0 += __shfl_xor_sync(0xffffffffu, r0, 2);
        r1 += __shfl_xor_sync(0xffffffffu, r1, 1);
        r1 += __shfl_xor_sync(0xffffffffu, r1, 2);
        if ((lane & 3) == 0) {
            int r = warpM * 64 + i * 16 + (lane >> 2);
            su[warpN * 128 + r]     = r0;
            su[warpN * 128 + r + 8] = r1;
        }
    }
    __syncthreads();
    if (tid < 128) {
        float s = su[tid] + su[128 + tid] + su[256 + tid] + su[384 + tid];
        g_pU[((size_t)(hop * NCHUNK + nch)) * ROWS + row0 + tid] = s;
    }
}

// ---------------------------------------------------------------
// fused: reduce pU -> softmax (recomputed per block, identical in all
// blocks of a batch) -> weighted column sums -> out. One fp32 X pass.
// grid (8 hchunk, BB), block 512. pU read with float4 (4 rows/thread).
// ---------------------------------------------------------------
__global__ void __launch_bounds__(512) colsum_out(const float* __restrict__ X,
                                                  float* __restrict__ out) {
    __shared__ float sa[2 * SS];            // alpha, both hops (16 KB)
    __shared__ float su[2 * 16 * 128];      // per-warp partials (16 KB)
    __shared__ float red[512];
    int hc = blockIdx.x, b = blockIdx.y;
    int tid = threadIdx.x, w = tid >> 5, lane = tid & 31;

    // --- softmax (both hops), recomputed identically in every hc block ---
#pragma unroll
    for (int hop = 0; hop < 2; hop++) {
        float4 u = make_float4(0.f, 0.f, 0.f, 0.f);
        {
            size_t base = (size_t)b * SS + tid * 4;
#pragma unroll
            for (int c = 0; c < NCHUNK; c++) {
                float4 p = *(const float4*)(g_pU + ((size_t)(hop * NCHUNK + c)) * ROWS + base);
                u.x += p.x; u.y += p.y; u.z += p.z; u.w += p.w;
            }
        }
        float m = fmaxf(fmaxf(u.x, u.y), fmaxf(u.z, u.w));
        red[tid] = m; __syncthreads();
        for (int o = 256; o > 0; o >>= 1) {
            if (tid < o) red[tid] = fmaxf(red[tid], red[tid + o]);
            __syncthreads();
        }
        float mx = red[0]; __syncthreads();
        float e0 = expf(u.x - mx), e1 = expf(u.y - mx);
        float e2 = expf(u.z - mx), e3 = expf(u.w - mx);
        red[tid] = (e0 + e1) + (e2 + e3); __syncthreads();
        for (int o = 256; o > 0; o >>= 1) {
            if (tid < o) red[tid] += red[tid + o];
            __syncthreads();
        }
        float inv = 1.f / red[0]; __syncthreads();
        *(float4*)(sa + hop * SS + tid * 4) =
            make_float4(e0 * inv, e1 * inv, e2 * inv, e3 * inv);
        __syncthreads();
    }

    // --- weighted column sums: warp w owns rows [w*128,(w+1)*128) ---
    int h0 = hc * 128 + lane * 4;
    size_t base = ((size_t)b * SS + (size_t)w * 128) * HH + h0;
    const float* a1 = sa + w * 128;
    const float* a2 = sa + SS + w * 128;
    float4 c1 = make_float4(0.f, 0.f, 0.f, 0.f);
    float4 c2 = make_float4(0.f, 0.f, 0.f, 0.f);
#pragma unroll 8
    for (int i = 0; i < 128; i++) {
        float4 x = __ldcs((const float4*)(X + base + (size_t)i * HH));
        float w1 = a1[i], w2 = a2[i];
        c1.x = fmaf(w1, x.x, c1.x); c1.y = fmaf(w1, x.y, c1.y);
        c1.z = fmaf(w1, x.z, c1.z); c1.w = fmaf(w1, x.w, c1.w);
        c2.x = fmaf(w2, x.x, c2.x); c2.y = fmaf(w2, x.y, c2.y);
        c2.z = fmaf(w2, x.z, c2.z); c2.w = fmaf(w2, x.w, c2.w);
    }
    *(float4*)(su + (0 * 16 + w) * 128 + lane * 4) = c1;
    *(float4*)(su + (1 * 16 + w) * 128 + lane * 4) = c2;
    __syncthreads();

    if (tid < 256) {
        int hop = tid >> 7, h = tid & 127;
        float s = 0.f;
#pragma unroll
        for (int ww = 0; ww < 16; ww++)
            s += su[(hop * 16 + ww) * 128 + h];
        out[(size_t)(1 + hop) * BB * HH + b * HH + hc * 128 + h] = s;
    }
}

// ---------------------------------------------------------------
extern "C" void kernel_launch(void* const* d_in, const int* in_sizes, int n_in,
                              void* d_out, int out_size) {
    (void)in_sizes; (void)n_in; (void)out_size;
    const float* X   = (const float*)d_in[0];
    const float* q   = (const float*)d_in[1];
    const float* W1  = (const float*)d_in[2];
    const float* Wm1 = (const float*)d_in[3];
    const float* Wh1 = (const float*)d_in[4];
    const float* W2  = (const float*)d_in[5];
    const float* Wm2 = (const float*)d_in[6];
    const float* Wh2 = (const float*)d_in[7];
    float* out = (float*)d_out;

    cudaFuncSetAttribute(gemm_mma, cudaFuncAttributeMaxDynamicSharedMemorySize, SM_TOTAL);

    conv_fused<<<2560, 256>>>(X, W1, W2);
    prep_v_part<<<dim3(8, VKS, 2), 256>>>(Wm1, Wm2, q);
    finalize_v<<<2 * BB * HH / 256, 256>>>(Wh1, Wh2, out);

    gemm_mma<<<dim3(NCHUNK * 2, ROWS / 128), 256, SM_TOTAL>>>();

    colsum_out<<<dim3(8, BB), 512>>>(X, out);
}